// round 15
// baseline (speedup 1.0000x reference)
#include <cuda_runtime.h>
#include <cuda_fp16.h>
#include <math.h>
#include <stdint.h>

#define NN 4096      // nodes
#define FIN 4096     // input features
#define HD 128       // hidden / emb
#define RR 8         // relations
#define GGRP 3       // groups
#define NE 65536     // edges
#define NCOLS 1152   // 8*128 + 128
#define LAMDA 0.01f
#define EPSN 1e-5f

// GEMM tiling: 128x128 CTA tile, 256 threads, BK=64, 2-stage, 2 CTAs/SM
#define BMT 128
#define BNT 128
#define BKT 64
#define STG 2
#define STAGE_B (BMT * BKT * 2 + BNT * BKT * 2)   // 32768 bytes per stage
#define GEMM_SMEM (STG * STAGE_B + 128)

// ---------------- scratch ------------------------------------------------------
__device__ __align__(16) __half g_Ah[(size_t)NN * FIN];      // x as fp16
__device__ __align__(16) __half g_Bth[(size_t)NCOLS * FIN];  // B^T packed [n, k] fp16
__device__ __align__(16) __half g_h2h[NN * HD];              // post-DGN+relu fp16
__device__ int   g_cnt[NN * RR];       // per (dst, r) edge counts (normalization)
__device__ float g_invc[NN * RR];      // 1/max(cnt,1)
__device__ int   g_cnt2[NN * RR];      // per (src, r) edge counts (CSR)
__device__ int   g_off[NN * RR];       // CSR offsets by (src, r)
__device__ int   g_cur[NN * RR];       // fill cursors
__device__ int   g_edst[NE];           // CSR payload: dst node per edge
__device__ float g_h[NN * HD];
__device__ float g_s[NN * GGRP];
__device__ float g_sum[GGRP * HD];
__device__ float g_sq[GGRP * HD];

// ---------------- PTX helpers --------------------------------------------------
__device__ __forceinline__ uint32_t smem_u32(const void* p) {
    uint32_t a;
    asm("{ .reg .u64 t; cvta.to.shared.u64 t, %1; cvt.u32.u64 %0, t; }" : "=r"(a) : "l"(p));
    return a;
}
__device__ __forceinline__ void cp16(uint32_t d, const void* s) {
    asm volatile("cp.async.cg.shared.global [%0], [%1], 16;" :: "r"(d), "l"(s));
}
__device__ __forceinline__ void ldsm4(uint32_t& r0, uint32_t& r1, uint32_t& r2, uint32_t& r3,
                                      uint32_t a) {
    asm volatile("ldmatrix.sync.aligned.m8n8.x4.shared.b16 {%0,%1,%2,%3}, [%4];"
        : "=r"(r0), "=r"(r1), "=r"(r2), "=r"(r3) : "r"(a));
}
__device__ __forceinline__ void mma16816(float* d, const uint32_t* a, uint32_t b0, uint32_t b1) {
    asm volatile("mma.sync.aligned.m16n8k16.row.col.f32.f16.f16.f32 "
        "{%0,%1,%2,%3}, {%4,%5,%6,%7}, {%8,%9}, {%0,%1,%2,%3};"
        : "+f"(d[0]), "+f"(d[1]), "+f"(d[2]), "+f"(d[3])
        : "r"(a[0]), "r"(a[1]), "r"(a[2]), "r"(a[3]), "r"(b0), "r"(b1));
}
__device__ __forceinline__ void red2(float* p, float x, float y) {
    asm volatile("red.global.add.v2.f32 [%0], {%1,%2};"
        :: "l"(p), "f"(x), "f"(y) : "memory");
}

// ---------------- HMMA GEMM + fully fused epilogue ------------------------------
// A[M,K] @ Bt[1152,K]^T. Relation block r (n0 = r*128, r<8): rows are scatter-
// added (scaled by 1/cnt[dst,r]) to dsth[dst] via the (src,r) CSR.
// Root block (n0>=1024): red-add acc+bias onto zeroed dsth.
__global__ __launch_bounds__(256, 2) void gemm_hmma(
    const __half* __restrict__ A, const __half* __restrict__ Bt, int K,
    const float* __restrict__ bias, float* __restrict__ dsth)
{
    extern __shared__ char smem_raw[];
    uint32_t sb = (smem_u32(smem_raw) + 127u) & ~127u;
    const int tid = threadIdx.x;
    const int lane = tid & 31;
    const int w = tid >> 5;
    const int m0 = blockIdx.y * BMT;
    const int n0 = blockIdx.x * BNT;
    const int wm = (w >> 2) * 64;     // warp tile 64x32, 2x4 warp grid
    const int wn = (w & 3) * 32;
    const int T = K >> 6;

    const int r7 = lane & 7;
    const int mat01 = (lane >> 3) & 1;
    const int mat2 = (lane >> 4) & 1;

    float acc[4][4][4];
#pragma unroll
    for (int i = 0; i < 4; i++)
#pragma unroll
        for (int j = 0; j < 4; j++)
#pragma unroll
            for (int c = 0; c < 4; c++) acc[i][j][c] = 0.f;

    auto ld_stage = [&](int buf, int t) {
        uint32_t base = sb + buf * STAGE_B;
        int k0 = t << 6;
#pragma unroll
        for (int i = 0; i < 4; i++) {
            int idx = tid + i * 256;
            int row = idx >> 3;
            int u = idx & 7;
            int su = u ^ (row & 7);
            cp16(base + row * 128 + su * 16,
                 A + (size_t)(m0 + row) * K + k0 + u * 8);
            cp16(base + BMT * BKT * 2 + row * 128 + su * 16,
                 Bt + (size_t)(n0 + row) * K + k0 + u * 8);
        }
    };

    ld_stage(0, 0);
    asm volatile("cp.async.commit_group;");

    for (int t = 0; t < T; t++) {
        asm volatile("cp.async.wait_group 0;");
        __syncthreads();   // chunk t visible; chunk t-1 compute done

        int pf = t + 1;
        if (pf < T) {
            ld_stage(pf & 1, pf);
            asm volatile("cp.async.commit_group;");
        }

        uint32_t Ab = sb + (t & 1) * STAGE_B;
        uint32_t Bb = Ab + BMT * BKT * 2;

#pragma unroll
        for (int ks = 0; ks < 4; ks++) {
            const int u = ks * 2 + mat2;
            const int su16 = ((u ^ r7) * 16);

            uint32_t a[4][4];
#pragma unroll
            for (int i = 0; i < 4; i++) {
                int mrow = wm + i * 16 + mat01 * 8 + r7;
                ldsm4(a[i][0], a[i][1], a[i][2], a[i][3], Ab + mrow * 128 + su16);
            }
            uint32_t b[2][4];
#pragma unroll
            for (int j2 = 0; j2 < 2; j2++) {
                int nrow = wn + j2 * 16 + mat01 * 8 + r7;
                ldsm4(b[j2][0], b[j2][1], b[j2][2], b[j2][3], Bb + nrow * 128 + su16);
            }
#pragma unroll
            for (int i = 0; i < 4; i++)
#pragma unroll
                for (int j = 0; j < 4; j++) {
                    mma16816(acc[i][j], a[i], b[j >> 1][j & 1], b[j >> 1][(j & 1) + 2]);
                }
        }
    }

    if (n0 >= RR * HD) {
        // root block: red-add acc+bias onto zeroed dsth
#pragma unroll
        for (int i = 0; i < 4; i++)
#pragma unroll
            for (int j = 0; j < 4; j++) {
                int m = m0 + wm + i * 16 + (lane >> 2);
                int hh = wn + j * 8 + (lane & 3) * 2;
                float b0v = bias[hh], b1v = bias[hh + 1];
                float* p = dsth + (size_t)m * HD + hh;
                red2(p, acc[i][j][0] + b0v, acc[i][j][1] + b1v);
                red2(p + (size_t)8 * HD, acc[i][j][2] + b0v, acc[i][j][3] + b1v);
            }
    } else {
        // relation block r: scatter rows to dst nodes via CSR
        const int r = n0 >> 7;
        const int hbase = (lane & 3) * 2;
#pragma unroll
        for (int i = 0; i < 4; i++) {
#pragma unroll
            for (int half = 0; half < 2; half++) {
                int m = m0 + wm + i * 16 + (lane >> 2) + half * 8;
                int key = m * RR + r;
                int beg = g_off[key];
                int num = g_cnt2[key];
                for (int e = 0; e < num; e++) {
                    int d = g_edst[beg + e];
                    float ic = g_invc[d * RR + r];
                    float* bp = dsth + (size_t)d * HD;
#pragma unroll
                    for (int j = 0; j < 4; j++) {
                        red2(bp + wn + j * 8 + hbase,
                             acc[i][j][half * 2] * ic, acc[i][j][half * 2 + 1] * ic);
                    }
                }
            }
        }
    }
}

// ---------------- conversion / packing -----------------------------------------
__global__ void conv_x(const float* __restrict__ x) {
    size_t i = (size_t)blockIdx.x * 256 + threadIdx.x;   // NN*FIN/4
    float4 v = ((const float4*)x)[i];
    __half2* dst = (__half2*)g_Ah;
    dst[i * 2 + 0] = __floats2half2_rn(v.x, v.y);
    dst[i * 2 + 1] = __floats2half2_rn(v.z, v.w);
}

// Coalesced transpose pack: Bth[z*128 + h][k] = src[k][h]
__global__ void pack_BtT(const float* __restrict__ W, const float* __restrict__ root, int K) {
    __shared__ float t[32][33];
    int z = blockIdx.z;
    const float* base = (z < RR) ? (W + (size_t)z * K * HD) : root;
    int k0 = blockIdx.x * 32, h0 = blockIdx.y * 32;
#pragma unroll
    for (int i = threadIdx.y; i < 32; i += 8)
        t[i][threadIdx.x] = base[(size_t)(k0 + i) * HD + h0 + threadIdx.x];
    __syncthreads();
#pragma unroll
    for (int i = threadIdx.y; i < 32; i += 8) {
        int n = z * HD + h0 + i;
        g_Bth[(size_t)n * K + k0 + threadIdx.x] = __float2half_rn(t[threadIdx.x][i]);
    }
}

// ---------------- graph preprocessing -------------------------------------------
__global__ void count_both(const int* __restrict__ ei, const int* __restrict__ et) {
    int e = blockIdx.x * 256 + threadIdx.x;
    if (e < NE) {
        int s = ei[e], d = ei[NE + e], r = et[e];
        atomicAdd(&g_cnt[d * RR + r], 1);
        atomicAdd(&g_cnt2[s * RR + r], 1);
    }
}
__global__ void invc_k() {
    int i = blockIdx.x * 256 + threadIdx.x;
    if (i < NN * RR) g_invc[i] = 1.f / fmaxf((float)g_cnt[i], 1.f);
}
// single-block exclusive scan of g_cnt2 (32768 = 1024 x 32) into g_off
__global__ void scan_k() {
    __shared__ int ps[1024];
    int t = threadIdx.x;
    int loc[32];
    int s = 0;
    int base = t * 32;
#pragma unroll
    for (int k = 0; k < 32; k++) { loc[k] = g_cnt2[base + k]; s += loc[k]; }
    ps[t] = s;
    __syncthreads();
    for (int o = 1; o < 1024; o <<= 1) {
        int v = (t >= o) ? ps[t - o] : 0;
        __syncthreads();
        ps[t] += v;
        __syncthreads();
    }
    int run = ps[t] - s;   // exclusive prefix for this thread's chunk
#pragma unroll
    for (int k = 0; k < 32; k++) { g_off[base + k] = run; run += loc[k]; }
}
__global__ void fill_k(const int* __restrict__ ei, const int* __restrict__ et) {
    int e = blockIdx.x * 256 + threadIdx.x;
    if (e < NE) {
        int s = ei[e], d = ei[NE + e], r = et[e];
        int key = s * RR + r;
        int pos = atomicAdd(&g_cur[key], 1);
        g_edst[g_off[key] + pos] = d;
    }
}

// ---------------- DiffGroupNorm -------------------------------------------------
__global__ void softmax_s(const float* __restrict__ lin_w, const float* __restrict__ lin_b) {
    int n = blockIdx.x;
    int t = threadIdx.x;  // 128
    float hv = g_h[n * HD + t];
    float p0 = hv * lin_w[t * GGRP + 0];
    float p1 = hv * lin_w[t * GGRP + 1];
    float p2 = hv * lin_w[t * GGRP + 2];
#pragma unroll
    for (int o = 16; o; o >>= 1) {
        p0 += __shfl_down_sync(0xffffffffu, p0, o);
        p1 += __shfl_down_sync(0xffffffffu, p1, o);
        p2 += __shfl_down_sync(0xffffffffu, p2, o);
    }
    __shared__ float sm[4][3];
    if ((t & 31) == 0) { sm[t >> 5][0] = p0; sm[t >> 5][1] = p1; sm[t >> 5][2] = p2; }
    __syncthreads();
    if (t == 0) {
        float l0 = lin_b[0], l1 = lin_b[1], l2 = lin_b[2];
        for (int w = 0; w < 4; w++) { l0 += sm[w][0]; l1 += sm[w][1]; l2 += sm[w][2]; }
        float mx = fmaxf(l0, fmaxf(l1, l2));
        float e0 = expf(l0 - mx), e1 = expf(l1 - mx), e2 = expf(l2 - mx);
        float inv = 1.f / (e0 + e1 + e2);
        g_s[n * 3 + 0] = e0 * inv;
        g_s[n * 3 + 1] = e1 * inv;
        g_s[n * 3 + 2] = e2 * inv;
    }
}
__global__ void stats_k() {
    int t = threadIdx.x;
    int chunk = blockIdx.x;
    float sum0 = 0, sum1 = 0, sum2 = 0, sq0 = 0, sq1 = 0, sq2 = 0;
    for (int i = 0; i < 32; i++) {
        int n = chunk * 32 + i;
        float hv = g_h[n * HD + t];
        float s0 = g_s[n * 3 + 0], s1 = g_s[n * 3 + 1], s2 = g_s[n * 3 + 2];
        float v0 = s0 * hv, v1 = s1 * hv, v2 = s2 * hv;
        sum0 += v0; sq0 += v0 * v0;
        sum1 += v1; sq1 += v1 * v1;
        sum2 += v2; sq2 += v2 * v2;
    }
    atomicAdd(&g_sum[0 * HD + t], sum0);
    atomicAdd(&g_sum[1 * HD + t], sum1);
    atomicAdd(&g_sum[2 * HD + t], sum2);
    atomicAdd(&g_sq[0 * HD + t], sq0);
    atomicAdd(&g_sq[1 * HD + t], sq1);
    atomicAdd(&g_sq[2 * HD + t], sq2);
}
__global__ void h2_k(const float* __restrict__ bn_w, const float* __restrict__ bn_b) {
    __shared__ float a[GGRP * HD], dcoef[GGRP * HD];
    const float invN = 1.f / (float)NN;
    for (int i = threadIdx.x; i < GGRP * HD; i += 256) {
        float mean = g_sum[i] * invN;
        float var = g_sq[i] * invN - mean * mean;
        float av = bn_w[i] / sqrtf(var + EPSN);
        a[i] = av;
        dcoef[i] = bn_b[i] - mean * av;
    }
    __syncthreads();
    int idx = blockIdx.x * 256 + threadIdx.x;
    int n = idx >> 7, hh = idx & 127;
    float hv = g_h[idx];
    float s0 = g_s[n * 3 + 0], s1 = g_s[n * 3 + 1], s2 = g_s[n * 3 + 2];
    float aa = s0 * a[hh] + s1 * a[HD + hh] + s2 * a[2 * HD + hh];
    float cc = dcoef[hh] + dcoef[HD + hh] + dcoef[2 * HD + hh];
    float v = fmaxf(hv * (1.f + LAMDA * aa) + LAMDA * cc, 0.f);
    g_h2h[idx] = __float2half_rn(v);
}

// ---------------- launch --------------------------------------------------------
extern "C" void kernel_launch(void* const* d_in, const int* in_sizes, int n_in,
                              void* d_out, int out_size) {
    const float* x      = (const float*)d_in[0];
    const int*   ei     = (const int*)d_in[1];
    const int*   et     = (const int*)d_in[2];
    const float* W1     = (const float*)d_in[3];
    const float* root1  = (const float*)d_in[4];
    const float* b1     = (const float*)d_in[5];
    const float* lin_w  = (const float*)d_in[6];
    const float* lin_b  = (const float*)d_in[7];
    const float* bn_w   = (const float*)d_in[8];
    const float* bn_b   = (const float*)d_in[9];
    const float* W2     = (const float*)d_in[10];
    const float* root2  = (const float*)d_in[11];
    const float* b2     = (const float*)d_in[12];
    float* out = (float*)d_out;

    float *sump, *sqp, *hp;
    int *cntp, *cnt2p, *curp;
    __half *Ahp, *Bthp, *h2hp;
    cudaGetSymbolAddress((void**)&cntp, g_cnt);
    cudaGetSymbolAddress((void**)&cnt2p, g_cnt2);
    cudaGetSymbolAddress((void**)&curp, g_cur);
    cudaGetSymbolAddress((void**)&sump, g_sum);
    cudaGetSymbolAddress((void**)&sqp, g_sq);
    cudaGetSymbolAddress((void**)&hp, g_h);
    cudaGetSymbolAddress((void**)&Ahp, g_Ah);
    cudaGetSymbolAddress((void**)&Bthp, g_Bth);
    cudaGetSymbolAddress((void**)&h2hp, g_h2h);

    cudaFuncSetAttribute(gemm_hmma, cudaFuncAttributeMaxDynamicSharedMemorySize, GEMM_SMEM);

    // zero scratch (memset nodes)
    cudaMemsetAsync(cntp, 0, NN * RR * sizeof(int));
    cudaMemsetAsync(cnt2p, 0, NN * RR * sizeof(int));
    cudaMemsetAsync(curp, 0, NN * RR * sizeof(int));
    cudaMemsetAsync(sump, 0, GGRP * HD * sizeof(float));
    cudaMemsetAsync(sqp, 0, GGRP * HD * sizeof(float));
    cudaMemsetAsync(hp, 0, NN * HD * sizeof(float));
    cudaMemsetAsync(out, 0, NN * HD * sizeof(float));

    // CSR build (shared by both layers)
    count_both<<<NE / 256, 256>>>(ei, et);
    invc_k<<<(NN * RR + 255) / 256, 256>>>();
    scan_k<<<1, 1024>>>();
    fill_k<<<NE / 256, 256>>>(ei, et);

    // layer 1: fused GEMM + scatter into h
    conv_x<<<(NN * FIN / 4) / 256, 256>>>(x);
    {
        dim3 g(FIN / 32, HD / 32, RR + 1);
        pack_BtT<<<g, dim3(32, 8)>>>(W1, root1, FIN);
    }
    {
        dim3 grid(NCOLS / BNT, NN / BMT);
        gemm_hmma<<<grid, 256, GEMM_SMEM>>>(Ahp, Bthp, FIN, b1, hp);
    }

    // DiffGroupNorm + relu
    softmax_s<<<NN, 128>>>(lin_w, lin_b);
    stats_k<<<128, 128>>>();
    h2_k<<<(NN * HD) / 256, 256>>>(bn_w, bn_b);

    // layer 2: fused GEMM + scatter into out
    {
        dim3 g(HD / 32, HD / 32, RR + 1);
        pack_BtT<<<g, dim3(32, 8)>>>(W2, root2, HD);
    }
    {
        dim3 grid(NCOLS / BNT, NN / BMT);
        gemm_hmma<<<grid, 256, GEMM_SMEM>>>(h2hp, Bthp, HD, b2, out);
    }
}

// round 16
// speedup vs baseline: 1.2512x; 1.2512x over previous
#include <cuda_runtime.h>
#include <cuda_fp16.h>
#include <math.h>
#include <stdint.h>

#define NN 4096      // nodes
#define FIN 4096     // input features
#define HD 128       // hidden / emb
#define RR 8         // relations
#define GGRP 3       // groups
#define NE 65536     // edges
#define NCOLS 1152   // 8*128 + 128
#define LAMDA 0.01f
#define EPSN 1e-5f

// GEMM tiling: 128x128 CTA tile, 256 threads, BK=64, 2-stage, 2 CTAs/SM (best known)
#define BMT 128
#define BNT 128
#define BKT 64
#define STG 2
#define STAGE_B (BMT * BKT * 2 + BNT * BKT * 2)   // 32768 bytes per stage
#define GEMM_SMEM (STG * STAGE_B + 128)

// ---------------- scratch ------------------------------------------------------
__device__ __align__(16) __half g_Ah[(size_t)NN * FIN];      // x as fp16
__device__ __align__(16) __half g_Bth[(size_t)NCOLS * FIN];  // B^T packed [n, k] fp16
__device__ __align__(16) __half g_h2h[NN * HD];              // post-DGN+relu fp16
__device__ float g_Y[(size_t)NN * NCOLS];
__device__ int   g_cnt[NN * RR];
__device__ float g_h[NN * HD];
__device__ float g_s[NN * GGRP];
__device__ float g_sum[GGRP * HD];
__device__ float g_sq[GGRP * HD];

// ---------------- PTX helpers --------------------------------------------------
__device__ __forceinline__ uint32_t smem_u32(const void* p) {
    uint32_t a;
    asm("{ .reg .u64 t; cvta.to.shared.u64 t, %1; cvt.u32.u64 %0, t; }" : "=r"(a) : "l"(p));
    return a;
}
__device__ __forceinline__ void cp16(uint32_t d, const void* s) {
    asm volatile("cp.async.cg.shared.global [%0], [%1], 16;" :: "r"(d), "l"(s));
}
__device__ __forceinline__ void ldsm4(uint32_t& r0, uint32_t& r1, uint32_t& r2, uint32_t& r3,
                                      uint32_t a) {
    asm volatile("ldmatrix.sync.aligned.m8n8.x4.shared.b16 {%0,%1,%2,%3}, [%4];"
        : "=r"(r0), "=r"(r1), "=r"(r2), "=r"(r3) : "r"(a));
}
__device__ __forceinline__ void mma16816(float* d, const uint32_t* a, uint32_t b0, uint32_t b1) {
    asm volatile("mma.sync.aligned.m16n8k16.row.col.f32.f16.f16.f32 "
        "{%0,%1,%2,%3}, {%4,%5,%6,%7}, {%8,%9}, {%0,%1,%2,%3};"
        : "+f"(d[0]), "+f"(d[1]), "+f"(d[2]), "+f"(d[3])
        : "r"(a[0]), "r"(a[1]), "r"(a[2]), "r"(a[3]), "r"(b0), "r"(b1));
}
__device__ __forceinline__ void red4(float* p, float x, float y, float z, float w) {
    asm volatile("red.global.add.v4.f32 [%0], {%1,%2,%3,%4};"
        :: "l"(p), "f"(x), "f"(y), "f"(z), "f"(w) : "memory");
}

// ---------------- HMMA GEMM + fused root epilogue ------------------------------
// C[M,1152] = A[M,K] @ Bt[1152,K]^T.  Block-col 8 (n>=1024) goes to
// dsth[m*HD + n-1024] = acc + bias[n-1024] instead of Y.
__global__ __launch_bounds__(256, 2) void gemm_hmma(
    const __half* __restrict__ A, const __half* __restrict__ Bt,
    float* __restrict__ C, int K,
    const float* __restrict__ bias, float* __restrict__ dsth)
{
    extern __shared__ char smem_raw[];
    uint32_t sb = (smem_u32(smem_raw) + 127u) & ~127u;
    const int tid = threadIdx.x;
    const int lane = tid & 31;
    const int w = tid >> 5;
    const int m0 = blockIdx.y * BMT;
    const int n0 = blockIdx.x * BNT;
    const int wm = (w >> 2) * 64;     // warp tile 64x32, 2x4 warp grid
    const int wn = (w & 3) * 32;
    const int T = K >> 6;

    const int r7 = lane & 7;
    const int mat01 = (lane >> 3) & 1;
    const int mat2 = (lane >> 4) & 1;

    float acc[4][4][4];
#pragma unroll
    for (int i = 0; i < 4; i++)
#pragma unroll
        for (int j = 0; j < 4; j++)
#pragma unroll
            for (int c = 0; c < 4; c++) acc[i][j][c] = 0.f;

    auto ld_stage = [&](int buf, int t) {
        uint32_t base = sb + buf * STAGE_B;
        int k0 = t << 6;
#pragma unroll
        for (int i = 0; i < 4; i++) {
            int idx = tid + i * 256;
            int row = idx >> 3;
            int u = idx & 7;
            int su = u ^ (row & 7);
            cp16(base + row * 128 + su * 16,
                 A + (size_t)(m0 + row) * K + k0 + u * 8);
            cp16(base + BMT * BKT * 2 + row * 128 + su * 16,
                 Bt + (size_t)(n0 + row) * K + k0 + u * 8);
        }
    };

    ld_stage(0, 0);
    asm volatile("cp.async.commit_group;");

    for (int t = 0; t < T; t++) {
        asm volatile("cp.async.wait_group 0;");
        __syncthreads();   // chunk t visible; chunk t-1 compute done

        int pf = t + 1;
        if (pf < T) {
            ld_stage(pf & 1, pf);
            asm volatile("cp.async.commit_group;");
        }

        uint32_t Ab = sb + (t & 1) * STAGE_B;
        uint32_t Bb = Ab + BMT * BKT * 2;

#pragma unroll
        for (int ks = 0; ks < 4; ks++) {
            const int u = ks * 2 + mat2;
            const int su16 = ((u ^ r7) * 16);

            uint32_t a[4][4];
#pragma unroll
            for (int i = 0; i < 4; i++) {
                int mrow = wm + i * 16 + mat01 * 8 + r7;
                ldsm4(a[i][0], a[i][1], a[i][2], a[i][3], Ab + mrow * 128 + su16);
            }
            uint32_t b[2][4];
#pragma unroll
            for (int j2 = 0; j2 < 2; j2++) {
                int nrow = wn + j2 * 16 + mat01 * 8 + r7;
                ldsm4(b[j2][0], b[j2][1], b[j2][2], b[j2][3], Bb + nrow * 128 + su16);
            }
#pragma unroll
            for (int i = 0; i < 4; i++)
#pragma unroll
                for (int j = 0; j < 4; j++) {
                    mma16816(acc[i][j], a[i], b[j >> 1][j & 1], b[j >> 1][(j & 1) + 2]);
                }
        }
    }

    // epilogue: root block goes to dsth with bias; rest to C
    const bool is_root = (n0 >= RR * HD);
#pragma unroll
    for (int i = 0; i < 4; i++)
#pragma unroll
        for (int j = 0; j < 4; j++) {
            int m = m0 + wm + i * 16 + (lane >> 2);
            int n = n0 + wn + j * 8 + (lane & 3) * 2;
            if (is_root) {
                int hh = n - RR * HD;
                float b0v = bias[hh], b1v = bias[hh + 1];
                float* p = dsth + (size_t)m * HD + hh;
                *(float2*)p = make_float2(acc[i][j][0] + b0v, acc[i][j][1] + b1v);
                *(float2*)(p + (size_t)8 * HD) = make_float2(acc[i][j][2] + b0v, acc[i][j][3] + b1v);
            } else {
                float* p = C + (size_t)m * NCOLS + n;
                *(float2*)p = make_float2(acc[i][j][0], acc[i][j][1]);
                *(float2*)(p + (size_t)8 * NCOLS) = make_float2(acc[i][j][2], acc[i][j][3]);
            }
        }
}

// ---------------- conversion / packing -----------------------------------------
__global__ void conv_x(const float* __restrict__ x) {
    size_t i = (size_t)blockIdx.x * 256 + threadIdx.x;   // NN*FIN/4
    float4 v = ((const float4*)x)[i];
    __half2* dst = (__half2*)g_Ah;
    dst[i * 2 + 0] = __floats2half2_rn(v.x, v.y);
    dst[i * 2 + 1] = __floats2half2_rn(v.z, v.w);
}

// Coalesced transpose pack: Bth[z*128 + h][k] = src[k][h]
__global__ void pack_BtT(const float* __restrict__ W, const float* __restrict__ root, int K) {
    __shared__ float t[32][33];
    int z = blockIdx.z;
    const float* base = (z < RR) ? (W + (size_t)z * K * HD) : root;
    int k0 = blockIdx.x * 32, h0 = blockIdx.y * 32;
#pragma unroll
    for (int i = threadIdx.y; i < 32; i += 8)
        t[i][threadIdx.x] = base[(size_t)(k0 + i) * HD + h0 + threadIdx.x];
    __syncthreads();
#pragma unroll
    for (int i = threadIdx.y; i < 32; i += 8) {
        int n = z * HD + h0 + i;
        g_Bth[(size_t)n * K + k0 + threadIdx.x] = __float2half_rn(t[threadIdx.x][i]);
    }
}

// ---------------- graph / misc kernels ------------------------------------------
__global__ void count_edges(const int* __restrict__ ei, const int* __restrict__ et) {
    int e = blockIdx.x * 256 + threadIdx.x;
    if (e < NE) atomicAdd(&g_cnt[ei[NE + e] * RR + et[e]], 1);
}
// per-edge scaled scatter with vector red; inv-count computed inline
__global__ void scatter_direct(const float* __restrict__ Y,
                               const int* __restrict__ ei, const int* __restrict__ et,
                               float* __restrict__ dst_arr) {
    int idx = blockIdx.x * 256 + threadIdx.x;  // NE*32
    int e = idx >> 5, q = idx & 31;
    int src = ei[e];
    int d = ei[NE + e];
    int r = et[e];
    float c = (float)g_cnt[d * RR + r];        // warp-broadcast load
    float ic = 1.f / fmaxf(c, 1.f);
    float4 v = *(const float4*)(Y + (size_t)src * NCOLS + r * HD + q * 4);
    red4(dst_arr + (size_t)d * HD + q * 4, v.x * ic, v.y * ic, v.z * ic, v.w * ic);
}
// fused softmax(s) + batch-norm moment accumulation (one pass over h)
__global__ void dgn_stats(const float* __restrict__ lin_w, const float* __restrict__ lin_b) {
    int t = threadIdx.x;   // 128
    float w0 = lin_w[t * GGRP + 0], w1 = lin_w[t * GGRP + 1], w2 = lin_w[t * GGRP + 2];
    float sum0 = 0, sum1 = 0, sum2 = 0, sq0 = 0, sq1 = 0, sq2 = 0;
    __shared__ float sm[4][3];
    __shared__ float sv[3];
    for (int i = 0; i < 32; i++) {
        int n = blockIdx.x * 32 + i;
        float hv = g_h[n * HD + t];
        float p0 = hv * w0, p1 = hv * w1, p2 = hv * w2;
#pragma unroll
        for (int o = 16; o; o >>= 1) {
            p0 += __shfl_down_sync(0xffffffffu, p0, o);
            p1 += __shfl_down_sync(0xffffffffu, p1, o);
            p2 += __shfl_down_sync(0xffffffffu, p2, o);
        }
        if ((t & 31) == 0) { sm[t >> 5][0] = p0; sm[t >> 5][1] = p1; sm[t >> 5][2] = p2; }
        __syncthreads();
        if (t == 0) {
            float l0 = lin_b[0], l1 = lin_b[1], l2 = lin_b[2];
            for (int ww = 0; ww < 4; ww++) { l0 += sm[ww][0]; l1 += sm[ww][1]; l2 += sm[ww][2]; }
            float mx = fmaxf(l0, fmaxf(l1, l2));
            float e0 = expf(l0 - mx), e1 = expf(l1 - mx), e2 = expf(l2 - mx);
            float inv = 1.f / (e0 + e1 + e2);
            sv[0] = e0 * inv; sv[1] = e1 * inv; sv[2] = e2 * inv;
            g_s[n * 3 + 0] = sv[0];
            g_s[n * 3 + 1] = sv[1];
            g_s[n * 3 + 2] = sv[2];
        }
        __syncthreads();
        float v0 = sv[0] * hv, v1 = sv[1] * hv, v2 = sv[2] * hv;
        sum0 += v0; sq0 += v0 * v0;
        sum1 += v1; sq1 += v1 * v1;
        sum2 += v2; sq2 += v2 * v2;
        __syncthreads();   // all lanes consumed sv/sm before next iteration overwrites
    }
    atomicAdd(&g_sum[0 * HD + t], sum0);
    atomicAdd(&g_sum[1 * HD + t], sum1);
    atomicAdd(&g_sum[2 * HD + t], sum2);
    atomicAdd(&g_sq[0 * HD + t], sq0);
    atomicAdd(&g_sq[1 * HD + t], sq1);
    atomicAdd(&g_sq[2 * HD + t], sq2);
}
// h2 with inline BN-coef computation
__global__ void h2_k(const float* __restrict__ bn_w, const float* __restrict__ bn_b) {
    __shared__ float a[GGRP * HD], dcoef[GGRP * HD];
    const float invN = 1.f / (float)NN;
    for (int i = threadIdx.x; i < GGRP * HD; i += 256) {
        float mean = g_sum[i] * invN;
        float var = g_sq[i] * invN - mean * mean;
        float av = bn_w[i] / sqrtf(var + EPSN);
        a[i] = av;
        dcoef[i] = bn_b[i] - mean * av;
    }
    __syncthreads();
    int idx = blockIdx.x * 256 + threadIdx.x;
    int n = idx >> 7, hh = idx & 127;
    float hv = g_h[idx];
    float s0 = g_s[n * 3 + 0], s1 = g_s[n * 3 + 1], s2 = g_s[n * 3 + 2];
    float aa = s0 * a[hh] + s1 * a[HD + hh] + s2 * a[2 * HD + hh];
    float cc = dcoef[hh] + dcoef[HD + hh] + dcoef[2 * HD + hh];
    float v = fmaxf(hv * (1.f + LAMDA * aa) + LAMDA * cc, 0.f);
    g_h2h[idx] = __float2half_rn(v);
}

// ---------------- launch --------------------------------------------------------
extern "C" void kernel_launch(void* const* d_in, const int* in_sizes, int n_in,
                              void* d_out, int out_size) {
    const float* x      = (const float*)d_in[0];
    const int*   ei     = (const int*)d_in[1];
    const int*   et     = (const int*)d_in[2];
    const float* W1     = (const float*)d_in[3];
    const float* root1  = (const float*)d_in[4];
    const float* b1     = (const float*)d_in[5];
    const float* lin_w  = (const float*)d_in[6];
    const float* lin_b  = (const float*)d_in[7];
    const float* bn_w   = (const float*)d_in[8];
    const float* bn_b   = (const float*)d_in[9];
    const float* W2     = (const float*)d_in[10];
    const float* root2  = (const float*)d_in[11];
    const float* b2     = (const float*)d_in[12];
    float* out = (float*)d_out;

    float *Yp, *sump, *sqp, *hp;
    int* cntp;
    __half *Ahp, *Bthp, *h2hp;
    cudaGetSymbolAddress((void**)&Yp, g_Y);
    cudaGetSymbolAddress((void**)&cntp, g_cnt);
    cudaGetSymbolAddress((void**)&sump, g_sum);
    cudaGetSymbolAddress((void**)&sqp, g_sq);
    cudaGetSymbolAddress((void**)&hp, g_h);
    cudaGetSymbolAddress((void**)&Ahp, g_Ah);
    cudaGetSymbolAddress((void**)&Bthp, g_Bth);
    cudaGetSymbolAddress((void**)&h2hp, g_h2h);

    cudaFuncSetAttribute(gemm_hmma, cudaFuncAttributeMaxDynamicSharedMemorySize, GEMM_SMEM);

    // zeroing via memset nodes
    cudaMemsetAsync(cntp, 0, NN * RR * sizeof(int));
    cudaMemsetAsync(sump, 0, GGRP * HD * sizeof(float));
    cudaMemsetAsync(sqp, 0, GGRP * HD * sizeof(float));

    count_edges<<<NE / 256, 256>>>(ei, et);

    // layer 1: Y1 = x @ [W1_r ...] ; root part + b1 fused into h
    conv_x<<<(NN * FIN / 4) / 256, 256>>>(x);
    {
        dim3 g(FIN / 32, HD / 32, RR + 1);
        pack_BtT<<<g, dim3(32, 8)>>>(W1, root1, FIN);
    }
    {
        dim3 grid(NCOLS / BNT, NN / BMT);
        gemm_hmma<<<grid, 256, GEMM_SMEM>>>(Ahp, Bthp, Yp, FIN, b1, hp);
    }
    scatter_direct<<<(NE * 32) / 256, 256>>>(Yp, ei, et, hp);

    // DiffGroupNorm + relu (softmax + stats fused)
    dgn_stats<<<NN / 32, 128>>>(lin_w, lin_b);
    h2_k<<<(NN * HD) / 256, 256>>>(bn_w, bn_b);

    // layer 2: Y2 = h2 @ [W2_r ...] ; root part + b2 fused into out
    {
        dim3 g(HD / 32, HD / 32, RR + 1);
        pack_BtT<<<g, dim3(32, 8)>>>(W2, root2, HD);
    }
    {
        dim3 grid(NCOLS / BNT, NN / BMT);
        gemm_hmma<<<grid, 256, GEMM_SMEM>>>(h2hp, Bthp, Yp, HD, b2, out);
    }
    scatter_direct<<<(NE * 32) / 256, 256>>>(Yp, ei, et, out);
}

// round 17
// speedup vs baseline: 1.3420x; 1.0726x over previous
#include <cuda_runtime.h>
#include <cuda_fp16.h>
#include <math.h>
#include <stdint.h>

#define NN 4096      // nodes
#define FIN 4096     // input features
#define HD 128       // hidden / emb
#define RR 8         // relations
#define GGRP 3       // groups
#define NE 65536     // edges
#define NCOLS 1152   // 8*128 + 128
#define LAMDA 0.01f
#define EPSN 1e-5f

// GEMM tiling: 128x128 CTA tile, 256 threads, BK=64, 2-stage, 2 CTAs/SM (best known)
#define BMT 128
#define BNT 128
#define BKT 64
#define STG 2
#define STAGE_B (BMT * BKT * 2 + BNT * BKT * 2)   // 32768 bytes per stage
#define GEMM_SMEM (STG * STAGE_B + 128)

// ---------------- scratch ------------------------------------------------------
__device__ __align__(16) __half g_Ah[(size_t)NN * FIN];      // x as fp16
__device__ __align__(16) __half g_Bth[(size_t)NCOLS * FIN];  // B^T packed [n, k] fp16
__device__ __align__(16) __half g_h2h[NN * HD];              // post-DGN+relu fp16
__device__ float g_Y[(size_t)NN * NCOLS];
__device__ int   g_cnt[NN * RR];
__device__ float g_h[NN * HD];
__device__ float g_s[NN * GGRP];
__device__ float g_sum[GGRP * HD];
__device__ float g_sq[GGRP * HD];

// ---------------- PTX helpers --------------------------------------------------
__device__ __forceinline__ uint32_t smem_u32(const void* p) {
    uint32_t a;
    asm("{ .reg .u64 t; cvta.to.shared.u64 t, %1; cvt.u32.u64 %0, t; }" : "=r"(a) : "l"(p));
    return a;
}
__device__ __forceinline__ void cp16(uint32_t d, const void* s) {
    asm volatile("cp.async.cg.shared.global [%0], [%1], 16;" :: "r"(d), "l"(s));
}
__device__ __forceinline__ void ldsm4(uint32_t& r0, uint32_t& r1, uint32_t& r2, uint32_t& r3,
                                      uint32_t a) {
    asm volatile("ldmatrix.sync.aligned.m8n8.x4.shared.b16 {%0,%1,%2,%3}, [%4];"
        : "=r"(r0), "=r"(r1), "=r"(r2), "=r"(r3) : "r"(a));
}
__device__ __forceinline__ void mma16816(float* d, const uint32_t* a, uint32_t b0, uint32_t b1) {
    asm volatile("mma.sync.aligned.m16n8k16.row.col.f32.f16.f16.f32 "
        "{%0,%1,%2,%3}, {%4,%5,%6,%7}, {%8,%9}, {%0,%1,%2,%3};"
        : "+f"(d[0]), "+f"(d[1]), "+f"(d[2]), "+f"(d[3])
        : "r"(a[0]), "r"(a[1]), "r"(a[2]), "r"(a[3]), "r"(b0), "r"(b1));
}
__device__ __forceinline__ void red4(float* p, float x, float y, float z, float w) {
    asm volatile("red.global.add.v4.f32 [%0], {%1,%2,%3,%4};"
        :: "l"(p), "f"(x), "f"(y), "f"(z), "f"(w) : "memory");
}

// ---------------- HMMA GEMM + fused root epilogue ------------------------------
// C[M,1152] = A[M,K] @ Bt[1152,K]^T.  Block-col 8 (n>=1024) goes to
// dsth[m*HD + n-1024] = acc + bias[n-1024] instead of Y.
__global__ __launch_bounds__(256, 2) void gemm_hmma(
    const __half* __restrict__ A, const __half* __restrict__ Bt,
    float* __restrict__ C, int K,
    const float* __restrict__ bias, float* __restrict__ dsth)
{
    extern __shared__ char smem_raw[];
    uint32_t sb = (smem_u32(smem_raw) + 127u) & ~127u;
    const int tid = threadIdx.x;
    const int lane = tid & 31;
    const int w = tid >> 5;
    const int m0 = blockIdx.y * BMT;
    const int n0 = blockIdx.x * BNT;
    const int wm = (w >> 2) * 64;     // warp tile 64x32, 2x4 warp grid
    const int wn = (w & 3) * 32;
    const int T = K >> 6;

    const int r7 = lane & 7;
    const int mat01 = (lane >> 3) & 1;
    const int mat2 = (lane >> 4) & 1;

    float acc[4][4][4];
#pragma unroll
    for (int i = 0; i < 4; i++)
#pragma unroll
        for (int j = 0; j < 4; j++)
#pragma unroll
            for (int c = 0; c < 4; c++) acc[i][j][c] = 0.f;

    auto ld_stage = [&](int buf, int t) {
        uint32_t base = sb + buf * STAGE_B;
        int k0 = t << 6;
#pragma unroll
        for (int i = 0; i < 4; i++) {
            int idx = tid + i * 256;
            int row = idx >> 3;
            int u = idx & 7;
            int su = u ^ (row & 7);
            cp16(base + row * 128 + su * 16,
                 A + (size_t)(m0 + row) * K + k0 + u * 8);
            cp16(base + BMT * BKT * 2 + row * 128 + su * 16,
                 Bt + (size_t)(n0 + row) * K + k0 + u * 8);
        }
    };

    ld_stage(0, 0);
    asm volatile("cp.async.commit_group;");

    for (int t = 0; t < T; t++) {
        asm volatile("cp.async.wait_group 0;");
        __syncthreads();   // chunk t visible; chunk t-1 compute done

        int pf = t + 1;
        if (pf < T) {
            ld_stage(pf & 1, pf);
            asm volatile("cp.async.commit_group;");
        }

        uint32_t Ab = sb + (t & 1) * STAGE_B;
        uint32_t Bb = Ab + BMT * BKT * 2;

#pragma unroll
        for (int ks = 0; ks < 4; ks++) {
            const int u = ks * 2 + mat2;
            const int su16 = ((u ^ r7) * 16);

            // B fragments first...
            uint32_t b[2][4];
#pragma unroll
            for (int j2 = 0; j2 < 2; j2++) {
                int nrow = wn + j2 * 16 + mat01 * 8 + r7;
                ldsm4(b[j2][0], b[j2][1], b[j2][2], b[j2][3], Bb + nrow * 128 + su16);
            }
            // ...then per-i: LDSM(a[i]) immediately followed by its MMAs,
            // so MMAs of block i overlap the LDSM of block i+1.
#pragma unroll
            for (int i = 0; i < 4; i++) {
                uint32_t a[4];
                int mrow = wm + i * 16 + mat01 * 8 + r7;
                ldsm4(a[0], a[1], a[2], a[3], Ab + mrow * 128 + su16);
#pragma unroll
                for (int j = 0; j < 4; j++) {
                    mma16816(acc[i][j], a, b[j >> 1][j & 1], b[j >> 1][(j & 1) + 2]);
                }
            }
        }
    }

    // epilogue: root block goes to dsth with bias; rest to C
    const bool is_root = (n0 >= RR * HD);
#pragma unroll
    for (int i = 0; i < 4; i++)
#pragma unroll
        for (int j = 0; j < 4; j++) {
            int m = m0 + wm + i * 16 + (lane >> 2);
            int n = n0 + wn + j * 8 + (lane & 3) * 2;
            if (is_root) {
                int hh = n - RR * HD;
                float b0v = bias[hh], b1v = bias[hh + 1];
                float* p = dsth + (size_t)m * HD + hh;
                *(float2*)p = make_float2(acc[i][j][0] + b0v, acc[i][j][1] + b1v);
                *(float2*)(p + (size_t)8 * HD) = make_float2(acc[i][j][2] + b0v, acc[i][j][3] + b1v);
            } else {
                float* p = C + (size_t)m * NCOLS + n;
                *(float2*)p = make_float2(acc[i][j][0], acc[i][j][1]);
                *(float2*)(p + (size_t)8 * NCOLS) = make_float2(acc[i][j][2], acc[i][j][3]);
            }
        }
}

// ---------------- conversion / packing -----------------------------------------
__global__ void conv_x(const float* __restrict__ x) {
    size_t i = (size_t)blockIdx.x * 256 + threadIdx.x;   // NN*FIN/4
    float4 v = ((const float4*)x)[i];
    __half2* dst = (__half2*)g_Ah;
    dst[i * 2 + 0] = __floats2half2_rn(v.x, v.y);
    dst[i * 2 + 1] = __floats2half2_rn(v.z, v.w);
}

// Coalesced transpose pack: Bth[z*128 + h][k] = src[k][h]
__global__ void pack_BtT(const float* __restrict__ W, const float* __restrict__ root, int K) {
    __shared__ float t[32][33];
    int z = blockIdx.z;
    const float* base = (z < RR) ? (W + (size_t)z * K * HD) : root;
    int k0 = blockIdx.x * 32, h0 = blockIdx.y * 32;
#pragma unroll
    for (int i = threadIdx.y; i < 32; i += 8)
        t[i][threadIdx.x] = base[(size_t)(k0 + i) * HD + h0 + threadIdx.x];
    __syncthreads();
#pragma unroll
    for (int i = threadIdx.y; i < 32; i += 8) {
        int n = z * HD + h0 + i;
        g_Bth[(size_t)n * K + k0 + threadIdx.x] = __float2half_rn(t[threadIdx.x][i]);
    }
}

// ---------------- graph / misc kernels ------------------------------------------
__global__ void count_edges(const int* __restrict__ ei, const int* __restrict__ et) {
    int e = blockIdx.x * 256 + threadIdx.x;
    if (e < NE) atomicAdd(&g_cnt[ei[NE + e] * RR + et[e]], 1);
}
// per-edge scaled scatter with vector red; inv-count computed inline
__global__ void scatter_direct(const float* __restrict__ Y,
                               const int* __restrict__ ei, const int* __restrict__ et,
                               float* __restrict__ dst_arr) {
    int idx = blockIdx.x * 256 + threadIdx.x;  // NE*32
    int e = idx >> 5, q = idx & 31;
    int src = ei[e];
    int d = ei[NE + e];
    int r = et[e];
    float c = (float)g_cnt[d * RR + r];        // warp-broadcast load
    float ic = 1.f / fmaxf(c, 1.f);
    float4 v = *(const float4*)(Y + (size_t)src * NCOLS + r * HD + q * 4);
    red4(dst_arr + (size_t)d * HD + q * 4, v.x * ic, v.y * ic, v.z * ic, v.w * ic);
}
__global__ void softmax_s(const float* __restrict__ lin_w, const float* __restrict__ lin_b) {
    int n = blockIdx.x;
    int t = threadIdx.x;  // 128
    float hv = g_h[n * HD + t];
    float p0 = hv * lin_w[t * GGRP + 0];
    float p1 = hv * lin_w[t * GGRP + 1];
    float p2 = hv * lin_w[t * GGRP + 2];
#pragma unroll
    for (int o = 16; o; o >>= 1) {
        p0 += __shfl_down_sync(0xffffffffu, p0, o);
        p1 += __shfl_down_sync(0xffffffffu, p1, o);
        p2 += __shfl_down_sync(0xffffffffu, p2, o);
    }
    __shared__ float sm[4][3];
    if ((t & 31) == 0) { sm[t >> 5][0] = p0; sm[t >> 5][1] = p1; sm[t >> 5][2] = p2; }
    __syncthreads();
    if (t == 0) {
        float l0 = lin_b[0], l1 = lin_b[1], l2 = lin_b[2];
        for (int w = 0; w < 4; w++) { l0 += sm[w][0]; l1 += sm[w][1]; l2 += sm[w][2]; }
        float mx = fmaxf(l0, fmaxf(l1, l2));
        float e0 = expf(l0 - mx), e1 = expf(l1 - mx), e2 = expf(l2 - mx);
        float inv = 1.f / (e0 + e1 + e2);
        g_s[n * 3 + 0] = e0 * inv;
        g_s[n * 3 + 1] = e1 * inv;
        g_s[n * 3 + 2] = e2 * inv;
    }
}
__global__ void stats_k() {
    int t = threadIdx.x;
    int chunk = blockIdx.x;
    float sum0 = 0, sum1 = 0, sum2 = 0, sq0 = 0, sq1 = 0, sq2 = 0;
    for (int i = 0; i < 32; i++) {
        int n = chunk * 32 + i;
        float hv = g_h[n * HD + t];
        float s0 = g_s[n * 3 + 0], s1 = g_s[n * 3 + 1], s2 = g_s[n * 3 + 2];
        float v0 = s0 * hv, v1 = s1 * hv, v2 = s2 * hv;
        sum0 += v0; sq0 += v0 * v0;
        sum1 += v1; sq1 += v1 * v1;
        sum2 += v2; sq2 += v2 * v2;
    }
    atomicAdd(&g_sum[0 * HD + t], sum0);
    atomicAdd(&g_sum[1 * HD + t], sum1);
    atomicAdd(&g_sum[2 * HD + t], sum2);
    atomicAdd(&g_sq[0 * HD + t], sq0);
    atomicAdd(&g_sq[1 * HD + t], sq1);
    atomicAdd(&g_sq[2 * HD + t], sq2);
}
// h2 with inline BN-coef computation
__global__ void h2_k(const float* __restrict__ bn_w, const float* __restrict__ bn_b) {
    __shared__ float a[GGRP * HD], dcoef[GGRP * HD];
    const float invN = 1.f / (float)NN;
    for (int i = threadIdx.x; i < GGRP * HD; i += 256) {
        float mean = g_sum[i] * invN;
        float var = g_sq[i] * invN - mean * mean;
        float av = bn_w[i] / sqrtf(var + EPSN);
        a[i] = av;
        dcoef[i] = bn_b[i] - mean * av;
    }
    __syncthreads();
    int idx = blockIdx.x * 256 + threadIdx.x;
    int n = idx >> 7, hh = idx & 127;
    float hv = g_h[idx];
    float s0 = g_s[n * 3 + 0], s1 = g_s[n * 3 + 1], s2 = g_s[n * 3 + 2];
    float aa = s0 * a[hh] + s1 * a[HD + hh] + s2 * a[2 * HD + hh];
    float cc = dcoef[hh] + dcoef[HD + hh] + dcoef[2 * HD + hh];
    float v = fmaxf(hv * (1.f + LAMDA * aa) + LAMDA * cc, 0.f);
    g_h2h[idx] = __float2half_rn(v);
}

// ---------------- launch --------------------------------------------------------
extern "C" void kernel_launch(void* const* d_in, const int* in_sizes, int n_in,
                              void* d_out, int out_size) {
    const float* x      = (const float*)d_in[0];
    const int*   ei     = (const int*)d_in[1];
    const int*   et     = (const int*)d_in[2];
    const float* W1     = (const float*)d_in[3];
    const float* root1  = (const float*)d_in[4];
    const float* b1     = (const float*)d_in[5];
    const float* lin_w  = (const float*)d_in[6];
    const float* lin_b  = (const float*)d_in[7];
    const float* bn_w   = (const float*)d_in[8];
    const float* bn_b   = (const float*)d_in[9];
    const float* W2     = (const float*)d_in[10];
    const float* root2  = (const float*)d_in[11];
    const float* b2     = (const float*)d_in[12];
    float* out = (float*)d_out;

    float *Yp, *sump, *sqp, *hp;
    int* cntp;
    __half *Ahp, *Bthp, *h2hp;
    cudaGetSymbolAddress((void**)&Yp, g_Y);
    cudaGetSymbolAddress((void**)&cntp, g_cnt);
    cudaGetSymbolAddress((void**)&sump, g_sum);
    cudaGetSymbolAddress((void**)&sqp, g_sq);
    cudaGetSymbolAddress((void**)&hp, g_h);
    cudaGetSymbolAddress((void**)&Ahp, g_Ah);
    cudaGetSymbolAddress((void**)&Bthp, g_Bth);
    cudaGetSymbolAddress((void**)&h2hp, g_h2h);

    cudaFuncSetAttribute(gemm_hmma, cudaFuncAttributeMaxDynamicSharedMemorySize, GEMM_SMEM);

    // zeroing via memset nodes
    cudaMemsetAsync(cntp, 0, NN * RR * sizeof(int));
    cudaMemsetAsync(sump, 0, GGRP * HD * sizeof(float));
    cudaMemsetAsync(sqp, 0, GGRP * HD * sizeof(float));

    count_edges<<<NE / 256, 256>>>(ei, et);

    // layer 1: Y1 = x @ [W1_r ...] ; root part + b1 fused into h
    conv_x<<<(NN * FIN / 4) / 256, 256>>>(x);
    {
        dim3 g(FIN / 32, HD / 32, RR + 1);
        pack_BtT<<<g, dim3(32, 8)>>>(W1, root1, FIN);
    }
    {
        dim3 grid(NCOLS / BNT, NN / BMT);
        gemm_hmma<<<grid, 256, GEMM_SMEM>>>(Ahp, Bthp, Yp, FIN, b1, hp);
    }
    scatter_direct<<<(NE * 32) / 256, 256>>>(Yp, ei, et, hp);

    // DiffGroupNorm + relu
    softmax_s<<<NN, 128>>>(lin_w, lin_b);
    stats_k<<<128, 128>>>();
    h2_k<<<(NN * HD) / 256, 256>>>(bn_w, bn_b);

    // layer 2: Y2 = h2 @ [W2_r ...] ; root part + b2 fused into out
    {
        dim3 g(HD / 32, HD / 32, RR + 1);
        pack_BtT<<<g, dim3(32, 8)>>>(W2, root2, HD);
    }
    {
        dim3 grid(NCOLS / BNT, NN / BMT);
        gemm_hmma<<<grid, 256, GEMM_SMEM>>>(h2hp, Bthp, Yp, HD, b2, out);
    }
    scatter_direct<<<(NE * 32) / 256, 256>>>(Yp, ei, et, out);
}